// round 13
// baseline (speedup 1.0000x reference)
#include <cuda_runtime.h>
#include <cuda_fp16.h>
#include <math.h>

// ---------------------------------------------------------------------------
// FourierTransformLayer: out = real(ifft2( fft2(x) * W )),
//   W[c,k1,k2] = mask((k1+256)&511,(k2+256)&511) * param[c,...] / 512^2
//
// Real-input packing (z = a + i*b, W real conj-symmetric), 48 complex planes.
// Radix-8 register FFTs (512 = 8^3), 64 thr/FFT, 8 complex/thread, 2 smem
// exchanges. DIF fwd -> digit-reversed; weights baked digit-reversed; DIT inv.
// Spectrum in half2.
//
// R13: back to R10 structure. New skew SK(p)=p+8*(p>>6) + per-thread loop
// rotation on the contiguous pattern => ALL exchange patterns bank-conflict-
// free (verified mod-32 / mod-4-slot). Row-kernel exchanges in half2 (halves
// smem traffic; +4 quantization points, budget ~5e-4 < 1e-3). Redundant
// syncs removed (store set == just-read set).
// ---------------------------------------------------------------------------

#define N      512
#define HALF   256
#define NPK    48            // packed planes (96 real planes / 2)
#define PLANE  (N * N)
#define SK(p)  ((p) + (((p) >> 6) << 3))   // conflict-free skew, max 567

__device__ unsigned g_spec[(size_t)NPK * PLANE];  // half2 per element, 48 MB
__device__ float    g_wbr[3 * PLANE];             // weights, digit-reversed layout

__device__ __forceinline__ unsigned pack_h2(float2 a) {
    __half2 h = __floats2half2_rn(a.x, a.y);
    return *reinterpret_cast<unsigned*>(&h);
}
__device__ __forceinline__ float2 unpack_h2(unsigned u) {
    __half2 h = *reinterpret_cast<__half2*>(&u);
    return __half22float2(h);
}

// ---- packed f32x2 complex add/sub/scale ----
__device__ __forceinline__ float2 cadd(float2 a, float2 b) {
    float2 r;
    asm("{\n\t.reg .b64 ra, rb, rr;\n\t"
        "mov.b64 ra, {%2, %3};\n\t"
        "mov.b64 rb, {%4, %5};\n\t"
        "add.rn.f32x2 rr, ra, rb;\n\t"
        "mov.b64 {%0, %1}, rr;\n\t}"
        : "=f"(r.x), "=f"(r.y)
        : "f"(a.x), "f"(a.y), "f"(b.x), "f"(b.y));
    return r;
}
__device__ __forceinline__ float2 csub(float2 a, float2 b) {
    float2 r;
    asm("{\n\t.reg .b64 ra, rb, rr;\n\t"
        "mov.b64 ra, {%2, %3};\n\t"
        "mov.b64 rb, {%4, %5};\n\t"
        "sub.rn.f32x2 rr, ra, rb;\n\t"
        "mov.b64 {%0, %1}, rr;\n\t}"
        : "=f"(r.x), "=f"(r.y)
        : "f"(a.x), "f"(a.y), "f"(b.x), "f"(b.y));
    return r;
}
__device__ __forceinline__ float2 cscale(float2 a, float w) {
    float2 r;
    asm("{\n\t.reg .b64 ra, rb, rr;\n\t"
        "mov.b64 ra, {%2, %3};\n\t"
        "mov.b64 rb, {%4, %4};\n\t"
        "mul.rn.f32x2 rr, ra, rb;\n\t"
        "mov.b64 {%0, %1}, rr;\n\t}"
        : "=f"(r.x), "=f"(r.y)
        : "f"(a.x), "f"(a.y), "f"(w));
    return r;
}

__device__ __forceinline__ float2 cmul(float2 a, float2 b) {
    return make_float2(a.x * b.x - a.y * b.y, a.x * b.y + a.y * b.x);
}
// a * conj(b)
__device__ __forceinline__ float2 cmulc(float2 a, float2 b) {
    return make_float2(a.x * b.x + a.y * b.y, a.y * b.x - a.x * b.y);
}

// 8-point DFT, natural order in AND out. INV -> conjugate twiddles (unnormalized).
template<bool INV>
__device__ __forceinline__ void dft8(float2 v[8]) {
    const float s = 0.70710678118654752440f;
    float2 b0 = cadd(v[0], v[4]), t4 = csub(v[0], v[4]);
    float2 b1 = cadd(v[1], v[5]), t5 = csub(v[1], v[5]);
    float2 b2 = cadd(v[2], v[6]), t6 = csub(v[2], v[6]);
    float2 b3 = cadd(v[3], v[7]), t7 = csub(v[3], v[7]);
    float2 b4 = t4;
    float2 b5 = INV ? make_float2(s * (t5.x - t5.y), s * (t5.x + t5.y))
                    : make_float2(s * (t5.x + t5.y), s * (t5.y - t5.x));
    float2 b6 = INV ? make_float2(-t6.y, t6.x)
                    : make_float2(t6.y, -t6.x);
    float2 b7 = INV ? make_float2(-s * (t7.x + t7.y), s * (t7.x - t7.y))
                    : make_float2(s * (t7.y - t7.x), -s * (t7.x + t7.y));
    float2 c0 = cadd(b0, b2), u2 = csub(b0, b2);
    float2 c1 = cadd(b1, b3), u3 = csub(b1, b3);
    float2 c4 = cadd(b4, b6), u6 = csub(b4, b6);
    float2 c5 = cadd(b5, b7), u7 = csub(b5, b7);
    float2 c2 = u2;
    float2 c3 = INV ? make_float2(-u3.y, u3.x) : make_float2(u3.y, -u3.x);
    float2 c6 = u6;
    float2 c7 = INV ? make_float2(-u7.y, u7.x) : make_float2(u7.y, -u7.x);
    v[0] = cadd(c0, c1); v[4] = csub(c0, c1);
    v[2] = cadd(c2, c3); v[6] = csub(c2, c3);
    v[1] = cadd(c4, c5); v[5] = csub(c4, c5);
    v[3] = cadd(c6, c7); v[7] = csub(c6, c7);
}

// Sequential power chain: v[r] *= w1^r
__device__ __forceinline__ void twiddle_out(float2 v[8], float2 w1) {
    float2 w = w1;
    v[1] = cmul(v[1], w);
    #pragma unroll
    for (int r = 2; r < 8; ++r) {
        w = cmul(w, w1);
        v[r] = cmul(v[r], w);
    }
}

// v[q] *= conj(w1^q)
__device__ __forceinline__ void twiddle_in_conj(float2 v[8], float2 w1) {
    float2 w = w1;
    v[1] = cmulc(v[1], w);
    #pragma unroll
    for (int r = 2; r < 8; ++r) {
        w = cmul(w, w1);
        v[r] = cmulc(v[r], w);
    }
}

// ---------------------------------------------------------------------------
// Weight table in base-8 digit-reversed layout (both dims).
// ---------------------------------------------------------------------------
__device__ __forceinline__ int octrev9(int p) {
    return ((p & 7) << 6) | (p & 56) | ((p >> 6) & 7);
}

__global__ void k_weights(const float* __restrict__ param) {
    int idx = blockIdx.x * blockDim.x + threadIdx.x;
    if (idx >= 3 * PLANE) return;
    int c   = idx >> 18;
    int rem = idx & (PLANE - 1);
    int k1  = octrev9(rem >> 9);
    int k2  = octrev9(rem & (N - 1));
    int sh  = (k1 + HALF) & (N - 1);
    int sw  = (k2 + HALF) & (N - 1);

    float dh = fabsf((float)(sh - HALF));
    float dw = fabsf((float)(sw - HALF));
    float r2 = dh * dh + dw * dw;
    float mval;
    if (r2 <= 1.0f) {
        mval = 0.5f;                               // SMOOTHNESS
    } else {
        float dist = sqrtf(r2) * (1.0f / 256.0f);
        mval = fmaxf(1.0f, dist * 2.0f);           // dist / SMOOTHNESS
    }
    float pv = param[c * PLANE + sh * N + sw];
    g_wbr[idx] = mval * pv * (1.0f / (float)PLANE);
}

// ---------------------------------------------------------------------------
// Row forward FFT (radix-8 DIF) on packed planes z = a + i*b.
// 4 rows/block (256 threads). half2 smem exchanges. Output digit-reversed.
// ---------------------------------------------------------------------------
__global__ void __launch_bounds__(256, 6) k_row_fwd(const float* __restrict__ x) {
    __shared__ float2   LUT[N];
    __shared__ unsigned S[4 * 576];   // half2 exchange buffer

    int tid = threadIdx.x;
    {
        float s, c;
        sincospif(-(float)tid * (1.0f / 256.0f), &s, &c);
        LUT[tid] = make_float2(c, s);
        sincospif(-(float)(tid + 256) * (1.0f / 256.0f), &s, &c);
        LUT[tid + 256] = make_float2(c, s);
    }
    int rl = tid >> 6;
    int t  = tid & 63;
    unsigned* Sr = S + rl * 576;

    int prow = blockIdx.x * 4 + rl;
    int pi   = prow >> 9;
    int r    = prow & (N - 1);
    int bp   = pi / 3;
    int ch   = pi - 3 * bp;
    const float* xre = x + (size_t)(6 * bp + ch) * PLANE + (size_t)r * N;
    const float* xim = xre + (size_t)3 * PLANE;
    int h64 = (t >> 3) << 6;
    int j8  = t & 7;

    float2 v[8];
    #pragma unroll
    for (int q = 0; q < 8; ++q) {
        int p = t + (q << 6);
        v[q] = make_float2(xre[p], xim[p]);
    }
    __syncthreads();   // LUT ready

    // stage m=64 (j = t)
    dft8<false>(v);
    twiddle_out(v, LUT[t]);
    #pragma unroll
    for (int r8 = 0; r8 < 8; ++r8) Sr[SK(t + (r8 << 6))] = pack_h2(v[r8]);
    __syncthreads();
    #pragma unroll
    for (int q = 0; q < 8; ++q) v[q] = unpack_h2(Sr[SK(h64 + j8 + (q << 3))]);

    // stage m=8 (j = t&7); store set == just-read set -> no sync in between
    dft8<false>(v);
    twiddle_out(v, LUT[j8 << 3]);
    #pragma unroll
    for (int r8 = 0; r8 < 8; ++r8) Sr[SK(h64 + j8 + (r8 << 3))] = pack_h2(v[r8]);
    __syncthreads();
    // contiguous own-block read, loop rotated by t (conflict-free with SK)
    #pragma unroll
    for (int qq = 0; qq < 8; ++qq) {
        int q = (qq + t) & 7;
        v[q] = unpack_h2(Sr[SK((t << 3) + q)]);
    }

    // stage m=1
    dft8<false>(v);

    uint4* o = (uint4*)(g_spec + (size_t)prow * N + (t << 3));
    o[0] = make_uint4(pack_h2(v[0]), pack_h2(v[1]), pack_h2(v[2]), pack_h2(v[3]));
    o[1] = make_uint4(pack_h2(v[4]), pack_h2(v[5]), pack_h2(v[6]), pack_h2(v[7]));
}

// ---------------------------------------------------------------------------
// Fused column pass: fwd radix-8 DIF -> real weight multiply -> inv radix-8 DIT.
// Block = 8 columns of one packed plane; c = tid&7, u = tid>>3. fp32 smem.
// ---------------------------------------------------------------------------
__global__ void __launch_bounds__(512, 3) k_col_fused() {
    __shared__ float2 LUT[N];
    __shared__ float2 S[568 * 8];

    int tid  = threadIdx.x;
    {
        float s, c;
        sincospif(-(float)tid * (1.0f / 256.0f), &s, &c);
        LUT[tid] = make_float2(c, s);
    }
    int c    = tid & 7;
    int u    = tid >> 3;
    int img  = blockIdx.x >> 6;          // 0..47
    int col0 = (blockIdx.x & 63) << 3;
    int ch   = img % 3;

    unsigned* base = g_spec + (size_t)img * PLANE + col0 + c;
    int h64 = (u >> 3) << 6;
    int j8  = u & 7;

    float2 v[8];
    #pragma unroll
    for (int q = 0; q < 8; ++q) v[q] = unpack_h2(base[(size_t)(u + (q << 6)) * N]);
    __syncthreads();   // LUT ready

    // ---- forward: stage m=64 ----
    dft8<false>(v);
    twiddle_out(v, LUT[u]);
    #pragma unroll
    for (int r = 0; r < 8; ++r) S[(SK(u + (r << 6)) << 3) | c] = v[r];
    __syncthreads();
    #pragma unroll
    for (int q = 0; q < 8; ++q) v[q] = S[(SK(h64 + j8 + (q << 3)) << 3) | c];

    // ---- forward: stage m=8 (store set == read set) ----
    dft8<false>(v);
    twiddle_out(v, LUT[j8 << 3]);
    #pragma unroll
    for (int r = 0; r < 8; ++r) S[(SK(h64 + j8 + (r << 3)) << 3) | c] = v[r];
    __syncthreads();
    // contiguous own-block read, rotated by u
    #pragma unroll
    for (int qq = 0; qq < 8; ++qq) {
        int q = (qq + u) & 7;
        v[q] = S[(SK((u << 3) + q) << 3) | c];
    }

    // ---- forward m=1 -> weight -> inverse m=1, all in registers ----
    dft8<false>(v);
    const float* wp = g_wbr + (size_t)ch * PLANE + (size_t)(u << 3) * N + col0 + c;
    #pragma unroll
    for (int r = 0; r < 8; ++r) v[r] = cscale(v[r], wp[(size_t)r * N]);
    dft8<true>(v);

    // store back to own contiguous set, rotated (same addresses just read)
    #pragma unroll
    for (int rr = 0; rr < 8; ++rr) {
        int r = (rr + u) & 7;
        S[(SK((u << 3) + r) << 3) | c] = v[r];
    }
    __syncthreads();
    #pragma unroll
    for (int q = 0; q < 8; ++q) v[q] = S[(SK(h64 + j8 + (q << 3)) << 3) | c];

    // ---- inverse: stage m=8 (store set == read set) ----
    twiddle_in_conj(v, LUT[j8 << 3]);
    dft8<true>(v);
    #pragma unroll
    for (int r = 0; r < 8; ++r) S[(SK(h64 + j8 + (r << 3)) << 3) | c] = v[r];
    __syncthreads();
    #pragma unroll
    for (int q = 0; q < 8; ++q) v[q] = S[(SK(u + (q << 6)) << 3) | c];

    // ---- inverse: stage m=64 ----
    twiddle_in_conj(v, LUT[u]);
    dft8<true>(v);
    #pragma unroll
    for (int r = 0; r < 8; ++r) base[(size_t)(u + (r << 6)) * N] = pack_h2(v[r]);
}

// ---------------------------------------------------------------------------
// Row inverse FFT (radix-8 DIT, digit-reversed half2 input -> natural).
// 4 rows/block (256 threads). half2 smem exchanges. Real Re/Im stores.
// ---------------------------------------------------------------------------
__global__ void __launch_bounds__(256, 6) k_row_inv(float* __restrict__ out) {
    __shared__ float2   LUT[N];
    __shared__ unsigned S[4 * 576];

    int tid = threadIdx.x;
    {
        float s, c;
        sincospif(-(float)tid * (1.0f / 256.0f), &s, &c);
        LUT[tid] = make_float2(c, s);
        sincospif(-(float)(tid + 256) * (1.0f / 256.0f), &s, &c);
        LUT[tid + 256] = make_float2(c, s);
    }
    int rl = tid >> 6;
    int t  = tid & 63;
    unsigned* Sr = S + rl * 576;

    int prow = blockIdx.x * 4 + rl;
    int pi   = prow >> 9;
    int r    = prow & (N - 1);
    int bp   = pi / 3;
    int ch   = pi - 3 * bp;
    int h64  = (t >> 3) << 6;
    int j8   = t & 7;

    const uint4* in4 = (const uint4*)(g_spec + (size_t)prow * N + (t << 3));
    float2 v[8];
    {
        uint4 a0 = in4[0], a1 = in4[1];
        v[0] = unpack_h2(a0.x); v[1] = unpack_h2(a0.y);
        v[2] = unpack_h2(a0.z); v[3] = unpack_h2(a0.w);
        v[4] = unpack_h2(a1.x); v[5] = unpack_h2(a1.y);
        v[6] = unpack_h2(a1.z); v[7] = unpack_h2(a1.w);
    }

    // stage m=1; store own contiguous block, rotated by t
    dft8<true>(v);
    #pragma unroll
    for (int rr = 0; rr < 8; ++rr) {
        int r8 = (rr + t) & 7;
        Sr[SK((t << 3) + r8)] = pack_h2(v[r8]);
    }
    __syncthreads();   // also covers LUT init (first LUT use is below)
    #pragma unroll
    for (int q = 0; q < 8; ++q) v[q] = unpack_h2(Sr[SK(h64 + j8 + (q << 3))]);

    // stage m=8 (store set == read set)
    twiddle_in_conj(v, LUT[j8 << 3]);
    dft8<true>(v);
    #pragma unroll
    for (int r8 = 0; r8 < 8; ++r8) Sr[SK(h64 + j8 + (r8 << 3))] = pack_h2(v[r8]);
    __syncthreads();
    #pragma unroll
    for (int q = 0; q < 8; ++q) v[q] = unpack_h2(Sr[SK(t + (q << 6))]);

    // stage m=64
    twiddle_in_conj(v, LUT[t]);
    dft8<true>(v);

    float* ore = out + (size_t)(6 * bp + ch) * PLANE + (size_t)r * N;
    float* oim = ore + (size_t)3 * PLANE;
    #pragma unroll
    for (int r8 = 0; r8 < 8; ++r8) {
        int p = t + (r8 << 6);
        ore[p] = v[r8].x;
        oim[p] = v[r8].y;
    }
}

// ---------------------------------------------------------------------------
extern "C" void kernel_launch(void* const* d_in, const int* in_sizes, int n_in,
                              void* d_out, int out_size) {
    const float* x = (const float*)d_in[0];
    const float* p = (const float*)d_in[1];
    if (n_in >= 2 && in_sizes[0] < in_sizes[1]) { const float* t = x; x = p; p = t; }
    float* out = (float*)d_out;

    k_weights<<<(3 * PLANE + 255) / 256, 256>>>(p);
    k_row_fwd<<<NPK * N / 4, 256>>>(x);
    k_col_fused<<<NPK * (N / 8), 512>>>();
    k_row_inv<<<NPK * N / 4, 256>>>(out);
}

// round 15
// speedup vs baseline: 1.0122x; 1.0122x over previous
#include <cuda_runtime.h>
#include <cuda_fp16.h>
#include <math.h>

// ---------------------------------------------------------------------------
// FourierTransformLayer: out = real(ifft2( fft2(x) * W )),
//   W[c,k1,k2] = mask((k1+256)&511,(k2+256)&511) * param[c,...] / 512^2
//
// Real-input packing (z = a + i*b, W real conj-symmetric), 48 complex planes.
// Radix-8 register FFTs (512 = 8^3), 64 thr/FFT, 8 complex/thread, 2 smem
// exchanges. DIF fwd -> digit-reversed; weights baked digit-reversed; DIT inv.
// Spectrum in half2 (global only).
//
// R14 = R10 champion + the ONE validated R13 piece:
//   - fp32 shared exchanges (half2 exchanges reverted: they blew up ALU pipe)
//   - SK(p) = p + 8*(p>>6) skew + rotated contiguous-block loops ->
//     bank-conflict-free on all three exchange patterns (R13 ncu: L1 71->34%)
//   - redundant __syncthreads removed (store set == just-read set)
// ---------------------------------------------------------------------------

#define N      512
#define HALF   256
#define NPK    48            // packed planes (96 real planes / 2)
#define PLANE  (N * N)
#define SK(p)  ((p) + (((p) >> 6) << 3))   // conflict-free skew, max 567

__device__ unsigned g_spec[(size_t)NPK * PLANE];  // half2 per element, 48 MB
__device__ float    g_wbr[3 * PLANE];             // weights, digit-reversed layout

__device__ __forceinline__ unsigned pack_h2(float2 a) {
    __half2 h = __floats2half2_rn(a.x, a.y);
    return *reinterpret_cast<unsigned*>(&h);
}
__device__ __forceinline__ float2 unpack_h2(unsigned u) {
    __half2 h = *reinterpret_cast<__half2*>(&u);
    return __half22float2(h);
}

// ---- packed f32x2 complex add/sub/scale ----
__device__ __forceinline__ float2 cadd(float2 a, float2 b) {
    float2 r;
    asm("{\n\t.reg .b64 ra, rb, rr;\n\t"
        "mov.b64 ra, {%2, %3};\n\t"
        "mov.b64 rb, {%4, %5};\n\t"
        "add.rn.f32x2 rr, ra, rb;\n\t"
        "mov.b64 {%0, %1}, rr;\n\t}"
        : "=f"(r.x), "=f"(r.y)
        : "f"(a.x), "f"(a.y), "f"(b.x), "f"(b.y));
    return r;
}
__device__ __forceinline__ float2 csub(float2 a, float2 b) {
    float2 r;
    asm("{\n\t.reg .b64 ra, rb, rr;\n\t"
        "mov.b64 ra, {%2, %3};\n\t"
        "mov.b64 rb, {%4, %5};\n\t"
        "sub.rn.f32x2 rr, ra, rb;\n\t"
        "mov.b64 {%0, %1}, rr;\n\t}"
        : "=f"(r.x), "=f"(r.y)
        : "f"(a.x), "f"(a.y), "f"(b.x), "f"(b.y));
    return r;
}
__device__ __forceinline__ float2 cscale(float2 a, float w) {
    float2 r;
    asm("{\n\t.reg .b64 ra, rb, rr;\n\t"
        "mov.b64 ra, {%2, %3};\n\t"
        "mov.b64 rb, {%4, %4};\n\t"
        "mul.rn.f32x2 rr, ra, rb;\n\t"
        "mov.b64 {%0, %1}, rr;\n\t}"
        : "=f"(r.x), "=f"(r.y)
        : "f"(a.x), "f"(a.y), "f"(w));
    return r;
}

__device__ __forceinline__ float2 cmul(float2 a, float2 b) {
    return make_float2(a.x * b.x - a.y * b.y, a.x * b.y + a.y * b.x);
}
// a * conj(b)
__device__ __forceinline__ float2 cmulc(float2 a, float2 b) {
    return make_float2(a.x * b.x + a.y * b.y, a.y * b.x - a.x * b.y);
}

// 8-point DFT, natural order in AND out. INV -> conjugate twiddles (unnormalized).
template<bool INV>
__device__ __forceinline__ void dft8(float2 v[8]) {
    const float s = 0.70710678118654752440f;
    float2 b0 = cadd(v[0], v[4]), t4 = csub(v[0], v[4]);
    float2 b1 = cadd(v[1], v[5]), t5 = csub(v[1], v[5]);
    float2 b2 = cadd(v[2], v[6]), t6 = csub(v[2], v[6]);
    float2 b3 = cadd(v[3], v[7]), t7 = csub(v[3], v[7]);
    float2 b4 = t4;
    float2 b5 = INV ? make_float2(s * (t5.x - t5.y), s * (t5.x + t5.y))
                    : make_float2(s * (t5.x + t5.y), s * (t5.y - t5.x));
    float2 b6 = INV ? make_float2(-t6.y, t6.x)
                    : make_float2(t6.y, -t6.x);
    float2 b7 = INV ? make_float2(-s * (t7.x + t7.y), s * (t7.x - t7.y))
                    : make_float2(s * (t7.y - t7.x), -s * (t7.x + t7.y));
    float2 c0 = cadd(b0, b2), u2 = csub(b0, b2);
    float2 c1 = cadd(b1, b3), u3 = csub(b1, b3);
    float2 c4 = cadd(b4, b6), u6 = csub(b4, b6);
    float2 c5 = cadd(b5, b7), u7 = csub(b5, b7);
    float2 c2 = u2;
    float2 c3 = INV ? make_float2(-u3.y, u3.x) : make_float2(u3.y, -u3.x);
    float2 c6 = u6;
    float2 c7 = INV ? make_float2(-u7.y, u7.x) : make_float2(u7.y, -u7.x);
    v[0] = cadd(c0, c1); v[4] = csub(c0, c1);
    v[2] = cadd(c2, c3); v[6] = csub(c2, c3);
    v[1] = cadd(c4, c5); v[5] = csub(c4, c5);
    v[3] = cadd(c6, c7); v[7] = csub(c6, c7);
}

// Sequential power chain: v[r] *= w1^r
__device__ __forceinline__ void twiddle_out(float2 v[8], float2 w1) {
    float2 w = w1;
    v[1] = cmul(v[1], w);
    #pragma unroll
    for (int r = 2; r < 8; ++r) {
        w = cmul(w, w1);
        v[r] = cmul(v[r], w);
    }
}

// v[q] *= conj(w1^q)
__device__ __forceinline__ void twiddle_in_conj(float2 v[8], float2 w1) {
    float2 w = w1;
    v[1] = cmulc(v[1], w);
    #pragma unroll
    for (int r = 2; r < 8; ++r) {
        w = cmul(w, w1);
        v[r] = cmulc(v[r], w);
    }
}

// ---------------------------------------------------------------------------
// Weight table in base-8 digit-reversed layout (both dims).
// ---------------------------------------------------------------------------
__device__ __forceinline__ int octrev9(int p) {
    return ((p & 7) << 6) | (p & 56) | ((p >> 6) & 7);
}

__global__ void k_weights(const float* __restrict__ param) {
    int idx = blockIdx.x * blockDim.x + threadIdx.x;
    if (idx >= 3 * PLANE) return;
    int c   = idx >> 18;
    int rem = idx & (PLANE - 1);
    int k1  = octrev9(rem >> 9);
    int k2  = octrev9(rem & (N - 1));
    int sh  = (k1 + HALF) & (N - 1);
    int sw  = (k2 + HALF) & (N - 1);

    float dh = fabsf((float)(sh - HALF));
    float dw = fabsf((float)(sw - HALF));
    float r2 = dh * dh + dw * dw;
    float mval;
    if (r2 <= 1.0f) {
        mval = 0.5f;                               // SMOOTHNESS
    } else {
        float dist = sqrtf(r2) * (1.0f / 256.0f);
        mval = fmaxf(1.0f, dist * 2.0f);           // dist / SMOOTHNESS
    }
    float pv = param[c * PLANE + sh * N + sw];
    g_wbr[idx] = mval * pv * (1.0f / (float)PLANE);
}

// ---------------------------------------------------------------------------
// Row forward FFT (radix-8 DIF) on packed planes z = a + i*b.
// 4 rows/block (256 threads). fp32 smem exchanges. Output digit-reversed.
// ---------------------------------------------------------------------------
__global__ void __launch_bounds__(256, 6) k_row_fwd(const float* __restrict__ x) {
    __shared__ float2 LUT[N];
    __shared__ float2 S[4 * 568];

    int tid = threadIdx.x;
    {
        float s, c;
        sincospif(-(float)tid * (1.0f / 256.0f), &s, &c);
        LUT[tid] = make_float2(c, s);
        sincospif(-(float)(tid + 256) * (1.0f / 256.0f), &s, &c);
        LUT[tid + 256] = make_float2(c, s);
    }
    int rl = tid >> 6;
    int t  = tid & 63;
    float2* Sr = S + rl * 568;

    int prow = blockIdx.x * 4 + rl;
    int pi   = prow >> 9;
    int r    = prow & (N - 1);
    int bp   = pi / 3;
    int ch   = pi - 3 * bp;
    const float* xre = x + (size_t)(6 * bp + ch) * PLANE + (size_t)r * N;
    const float* xim = xre + (size_t)3 * PLANE;
    int h64 = (t >> 3) << 6;
    int j8  = t & 7;

    float2 v[8];
    #pragma unroll
    for (int q = 0; q < 8; ++q) {
        int p = t + (q << 6);
        v[q] = make_float2(xre[p], xim[p]);
    }
    __syncthreads();   // LUT ready

    // stage m=64 (j = t)
    dft8<false>(v);
    twiddle_out(v, LUT[t]);
    #pragma unroll
    for (int r8 = 0; r8 < 8; ++r8) Sr[SK(t + (r8 << 6))] = v[r8];
    __syncthreads();
    #pragma unroll
    for (int q = 0; q < 8; ++q) v[q] = Sr[SK(h64 + j8 + (q << 3))];

    // stage m=8 (j = t&7); store set == just-read set -> no sync in between
    dft8<false>(v);
    twiddle_out(v, LUT[j8 << 3]);
    #pragma unroll
    for (int r8 = 0; r8 < 8; ++r8) Sr[SK(h64 + j8 + (r8 << 3))] = v[r8];
    __syncthreads();
    // contiguous own-block read, loop rotated by t (conflict-free with SK)
    #pragma unroll
    for (int qq = 0; qq < 8; ++qq) {
        int q = (qq + t) & 7;
        v[q] = Sr[SK((t << 3) + q)];
    }

    // stage m=1
    dft8<false>(v);

    uint4* o = (uint4*)(g_spec + (size_t)prow * N + (t << 3));
    o[0] = make_uint4(pack_h2(v[0]), pack_h2(v[1]), pack_h2(v[2]), pack_h2(v[3]));
    o[1] = make_uint4(pack_h2(v[4]), pack_h2(v[5]), pack_h2(v[6]), pack_h2(v[7]));
}

// ---------------------------------------------------------------------------
// Fused column pass: fwd radix-8 DIF -> real weight multiply -> inv radix-8 DIT.
// Block = 8 columns of one packed plane; c = tid&7, u = tid>>3. fp32 smem.
// ---------------------------------------------------------------------------
__global__ void __launch_bounds__(512, 3) k_col_fused() {
    __shared__ float2 LUT[N];
    __shared__ float2 S[568 * 8];

    int tid  = threadIdx.x;
    {
        float s, c;
        sincospif(-(float)tid * (1.0f / 256.0f), &s, &c);
        LUT[tid] = make_float2(c, s);
    }
    int c    = tid & 7;
    int u    = tid >> 3;
    int img  = blockIdx.x >> 6;          // 0..47
    int col0 = (blockIdx.x & 63) << 3;
    int ch   = img % 3;

    unsigned* base = g_spec + (size_t)img * PLANE + col0 + c;
    int h64 = (u >> 3) << 6;
    int j8  = u & 7;

    float2 v[8];
    #pragma unroll
    for (int q = 0; q < 8; ++q) v[q] = unpack_h2(base[(size_t)(u + (q << 6)) * N]);
    __syncthreads();   // LUT ready

    // ---- forward: stage m=64 ----
    dft8<false>(v);
    twiddle_out(v, LUT[u]);
    #pragma unroll
    for (int r = 0; r < 8; ++r) S[(SK(u + (r << 6)) << 3) | c] = v[r];
    __syncthreads();
    #pragma unroll
    for (int q = 0; q < 8; ++q) v[q] = S[(SK(h64 + j8 + (q << 3)) << 3) | c];

    // ---- forward: stage m=8 (store set == read set) ----
    dft8<false>(v);
    twiddle_out(v, LUT[j8 << 3]);
    #pragma unroll
    for (int r = 0; r < 8; ++r) S[(SK(h64 + j8 + (r << 3)) << 3) | c] = v[r];
    __syncthreads();
    // contiguous own-block read, rotated by u
    #pragma unroll
    for (int qq = 0; qq < 8; ++qq) {
        int q = (qq + u) & 7;
        v[q] = S[(SK((u << 3) + q) << 3) | c];
    }

    // ---- forward m=1 -> weight -> inverse m=1, all in registers ----
    dft8<false>(v);
    const float* wp = g_wbr + (size_t)ch * PLANE + (size_t)(u << 3) * N + col0 + c;
    #pragma unroll
    for (int r = 0; r < 8; ++r) v[r] = cscale(v[r], wp[(size_t)r * N]);
    dft8<true>(v);

    // store back to own contiguous set, rotated (same addresses just read)
    #pragma unroll
    for (int rr = 0; rr < 8; ++rr) {
        int r = (rr + u) & 7;
        S[(SK((u << 3) + r) << 3) | c] = v[r];
    }
    __syncthreads();
    #pragma unroll
    for (int q = 0; q < 8; ++q) v[q] = S[(SK(h64 + j8 + (q << 3)) << 3) | c];

    // ---- inverse: stage m=8 (store set == read set) ----
    twiddle_in_conj(v, LUT[j8 << 3]);
    dft8<true>(v);
    #pragma unroll
    for (int r = 0; r < 8; ++r) S[(SK(h64 + j8 + (r << 3)) << 3) | c] = v[r];
    __syncthreads();
    #pragma unroll
    for (int q = 0; q < 8; ++q) v[q] = S[(SK(u + (q << 6)) << 3) | c];

    // ---- inverse: stage m=64 ----
    twiddle_in_conj(v, LUT[u]);
    dft8<true>(v);
    #pragma unroll
    for (int r = 0; r < 8; ++r) base[(size_t)(u + (r << 6)) * N] = pack_h2(v[r]);
}

// ---------------------------------------------------------------------------
// Row inverse FFT (radix-8 DIT, digit-reversed half2 input -> natural).
// 4 rows/block (256 threads). fp32 smem exchanges. Real Re/Im stores.
// ---------------------------------------------------------------------------
__global__ void __launch_bounds__(256, 6) k_row_inv(float* __restrict__ out) {
    __shared__ float2 LUT[N];
    __shared__ float2 S[4 * 568];

    int tid = threadIdx.x;
    {
        float s, c;
        sincospif(-(float)tid * (1.0f / 256.0f), &s, &c);
        LUT[tid] = make_float2(c, s);
        sincospif(-(float)(tid + 256) * (1.0f / 256.0f), &s, &c);
        LUT[tid + 256] = make_float2(c, s);
    }
    int rl = tid >> 6;
    int t  = tid & 63;
    float2* Sr = S + rl * 568;

    int prow = blockIdx.x * 4 + rl;
    int pi   = prow >> 9;
    int r    = prow & (N - 1);
    int bp   = pi / 3;
    int ch   = pi - 3 * bp;
    int h64  = (t >> 3) << 6;
    int j8   = t & 7;

    const uint4* in4 = (const uint4*)(g_spec + (size_t)prow * N + (t << 3));
    float2 v[8];
    {
        uint4 a0 = in4[0], a1 = in4[1];
        v[0] = unpack_h2(a0.x); v[1] = unpack_h2(a0.y);
        v[2] = unpack_h2(a0.z); v[3] = unpack_h2(a0.w);
        v[4] = unpack_h2(a1.x); v[5] = unpack_h2(a1.y);
        v[6] = unpack_h2(a1.z); v[7] = unpack_h2(a1.w);
    }

    // stage m=1; store own contiguous block, rotated by t
    dft8<true>(v);
    #pragma unroll
    for (int rr = 0; rr < 8; ++rr) {
        int r8 = (rr + t) & 7;
        Sr[SK((t << 3) + r8)] = v[r8];
    }
    __syncthreads();   // also covers LUT init (first LUT use is below)
    #pragma unroll
    for (int q = 0; q < 8; ++q) v[q] = Sr[SK(h64 + j8 + (q << 3))];

    // stage m=8 (store set == read set)
    twiddle_in_conj(v, LUT[j8 << 3]);
    dft8<true>(v);
    #pragma unroll
    for (int r8 = 0; r8 < 8; ++r8) Sr[SK(h64 + j8 + (r8 << 3))] = v[r8];
    __syncthreads();
    #pragma unroll
    for (int q = 0; q < 8; ++q) v[q] = Sr[SK(t + (q << 6))];

    // stage m=64
    twiddle_in_conj(v, LUT[t]);
    dft8<true>(v);

    float* ore = out + (size_t)(6 * bp + ch) * PLANE + (size_t)r * N;
    float* oim = ore + (size_t)3 * PLANE;
    #pragma unroll
    for (int r8 = 0; r8 < 8; ++r8) {
        int p = t + (r8 << 6);
        ore[p] = v[r8].x;
        oim[p] = v[r8].y;
    }
}

// ---------------------------------------------------------------------------
extern "C" void kernel_launch(void* const* d_in, const int* in_sizes, int n_in,
                              void* d_out, int out_size) {
    const float* x = (const float*)d_in[0];
    const float* p = (const float*)d_in[1];
    if (n_in >= 2 && in_sizes[0] < in_sizes[1]) { const float* t = x; x = p; p = t; }
    float* out = (float*)d_out;

    k_weights<<<(3 * PLANE + 255) / 256, 256>>>(p);
    k_row_fwd<<<NPK * N / 4, 256>>>(x);
    k_col_fused<<<NPK * (N / 8), 512>>>();
    k_row_inv<<<NPK * N / 4, 256>>>(out);
}

// round 16
// speedup vs baseline: 1.1547x; 1.1408x over previous
#include <cuda_runtime.h>
#include <cuda_fp16.h>
#include <math.h>

// ---------------------------------------------------------------------------
// FourierTransformLayer: out = real(ifft2( fft2(x) * W )),
//   W[c,k1,k2] = mask((k1+256)&511,(k2+256)&511) * param[c,...] / 512^2
//
// Real-input packing (z = a + i*b, W real conj-symmetric), 48 complex planes.
// Radix-8 register FFTs (512 = 8^3), 64 thr/FFT, 8 complex/thread, 2 smem
// exchanges per FFT. DIF fwd -> digit-reversed; weights baked digit-reversed;
// DIT inv. Spectrum in half2 (global only). Packed f32x2 butterflies.
//
// R16 = R10 arithmetic (bit-identical) + rotated-SLOT shared layout:
//   slot(j, B) = (j + B) & 7, addr = SK(8B) + slot, SK(p) = p + 8*(p>>6).
//   Conflict-free for ALL exchange patterns with STATIC v[] indexing
//   (R13/R14 rotation fixed conflicts but dynamic v[] indexing blew up ALU).
//   Twiddles computed directly (2 sincospif/thread) -> no smem LUT, one
//   less __syncthreads per kernel. Store-set==read-set syncs elided.
// ---------------------------------------------------------------------------

#define N      512
#define HALF   256
#define NPK    48            // packed planes (96 real planes / 2)
#define PLANE  (N * N)

__device__ unsigned g_spec[(size_t)NPK * PLANE];  // half2 per element, 48 MB
__device__ float    g_wbr[3 * PLANE];             // weights, digit-reversed layout

__device__ __forceinline__ unsigned pack_h2(float2 a) {
    __half2 h = __floats2half2_rn(a.x, a.y);
    return *reinterpret_cast<unsigned*>(&h);
}
__device__ __forceinline__ float2 unpack_h2(unsigned u) {
    __half2 h = *reinterpret_cast<__half2*>(&u);
    return __half22float2(h);
}

// ---- packed f32x2 complex add/sub/scale ----
__device__ __forceinline__ float2 cadd(float2 a, float2 b) {
    float2 r;
    asm("{\n\t.reg .b64 ra, rb, rr;\n\t"
        "mov.b64 ra, {%2, %3};\n\t"
        "mov.b64 rb, {%4, %5};\n\t"
        "add.rn.f32x2 rr, ra, rb;\n\t"
        "mov.b64 {%0, %1}, rr;\n\t}"
        : "=f"(r.x), "=f"(r.y)
        : "f"(a.x), "f"(a.y), "f"(b.x), "f"(b.y));
    return r;
}
__device__ __forceinline__ float2 csub(float2 a, float2 b) {
    float2 r;
    asm("{\n\t.reg .b64 ra, rb, rr;\n\t"
        "mov.b64 ra, {%2, %3};\n\t"
        "mov.b64 rb, {%4, %5};\n\t"
        "sub.rn.f32x2 rr, ra, rb;\n\t"
        "mov.b64 {%0, %1}, rr;\n\t}"
        : "=f"(r.x), "=f"(r.y)
        : "f"(a.x), "f"(a.y), "f"(b.x), "f"(b.y));
    return r;
}
__device__ __forceinline__ float2 cscale(float2 a, float w) {
    float2 r;
    asm("{\n\t.reg .b64 ra, rb, rr;\n\t"
        "mov.b64 ra, {%2, %3};\n\t"
        "mov.b64 rb, {%4, %4};\n\t"
        "mul.rn.f32x2 rr, ra, rb;\n\t"
        "mov.b64 {%0, %1}, rr;\n\t}"
        : "=f"(r.x), "=f"(r.y)
        : "f"(a.x), "f"(a.y), "f"(w));
    return r;
}

__device__ __forceinline__ float2 cmul(float2 a, float2 b) {
    return make_float2(a.x * b.x - a.y * b.y, a.x * b.y + a.y * b.x);
}
// a * conj(b)
__device__ __forceinline__ float2 cmulc(float2 a, float2 b) {
    return make_float2(a.x * b.x + a.y * b.y, a.y * b.x - a.x * b.y);
}

// 8-point DFT, natural order in AND out. INV -> conjugate twiddles (unnormalized).
template<bool INV>
__device__ __forceinline__ void dft8(float2 v[8]) {
    const float s = 0.70710678118654752440f;
    float2 b0 = cadd(v[0], v[4]), t4 = csub(v[0], v[4]);
    float2 b1 = cadd(v[1], v[5]), t5 = csub(v[1], v[5]);
    float2 b2 = cadd(v[2], v[6]), t6 = csub(v[2], v[6]);
    float2 b3 = cadd(v[3], v[7]), t7 = csub(v[3], v[7]);
    float2 b4 = t4;
    float2 b5 = INV ? make_float2(s * (t5.x - t5.y), s * (t5.x + t5.y))
                    : make_float2(s * (t5.x + t5.y), s * (t5.y - t5.x));
    float2 b6 = INV ? make_float2(-t6.y, t6.x)
                    : make_float2(t6.y, -t6.x);
    float2 b7 = INV ? make_float2(-s * (t7.x + t7.y), s * (t7.x - t7.y))
                    : make_float2(s * (t7.y - t7.x), -s * (t7.x + t7.y));
    float2 c0 = cadd(b0, b2), u2 = csub(b0, b2);
    float2 c1 = cadd(b1, b3), u3 = csub(b1, b3);
    float2 c4 = cadd(b4, b6), u6 = csub(b4, b6);
    float2 c5 = cadd(b5, b7), u7 = csub(b5, b7);
    float2 c2 = u2;
    float2 c3 = INV ? make_float2(-u3.y, u3.x) : make_float2(u3.y, -u3.x);
    float2 c6 = u6;
    float2 c7 = INV ? make_float2(-u7.y, u7.x) : make_float2(u7.y, -u7.x);
    v[0] = cadd(c0, c1); v[4] = csub(c0, c1);
    v[2] = cadd(c2, c3); v[6] = csub(c2, c3);
    v[1] = cadd(c4, c5); v[5] = csub(c4, c5);
    v[3] = cadd(c6, c7); v[7] = csub(c6, c7);
}

// Sequential power chain: v[r] *= w1^r
__device__ __forceinline__ void twiddle_out(float2 v[8], float2 w1) {
    float2 w = w1;
    v[1] = cmul(v[1], w);
    #pragma unroll
    for (int r = 2; r < 8; ++r) {
        w = cmul(w, w1);
        v[r] = cmul(v[r], w);
    }
}

// v[q] *= conj(w1^q)
__device__ __forceinline__ void twiddle_in_conj(float2 v[8], float2 w1) {
    float2 w = w1;
    v[1] = cmulc(v[1], w);
    #pragma unroll
    for (int r = 2; r < 8; ++r) {
        w = cmul(w, w1);
        v[r] = cmulc(v[r], w);
    }
}

// ---------------------------------------------------------------------------
// Weight table in base-8 digit-reversed layout (both dims).
// ---------------------------------------------------------------------------
__device__ __forceinline__ int octrev9(int p) {
    return ((p & 7) << 6) | (p & 56) | ((p >> 6) & 7);
}

__global__ void k_weights(const float* __restrict__ param) {
    int idx = blockIdx.x * blockDim.x + threadIdx.x;
    if (idx >= 3 * PLANE) return;
    int c   = idx >> 18;
    int rem = idx & (PLANE - 1);
    int k1  = octrev9(rem >> 9);
    int k2  = octrev9(rem & (N - 1));
    int sh  = (k1 + HALF) & (N - 1);
    int sw  = (k2 + HALF) & (N - 1);

    float dh = fabsf((float)(sh - HALF));
    float dw = fabsf((float)(sw - HALF));
    float r2 = dh * dh + dw * dw;
    float mval;
    if (r2 <= 1.0f) {
        mval = 0.5f;                               // SMOOTHNESS
    } else {
        float dist = sqrtf(r2) * (1.0f / 256.0f);
        mval = fmaxf(1.0f, dist * 2.0f);           // dist / SMOOTHNESS
    }
    float pv = param[c * PLANE + sh * N + sw];
    g_wbr[idx] = mval * pv * (1.0f / (float)PLANE);
}

// ---------------------------------------------------------------------------
// Row forward FFT (radix-8 DIF) on packed planes z = a + i*b.
// 4 rows/block (256 threads). fp32 smem, rotated-slot layout.
// ---------------------------------------------------------------------------
__global__ void __launch_bounds__(256, 6) k_row_fwd(const float* __restrict__ x) {
    __shared__ float2 S[4 * 568];

    int tid = threadIdx.x;
    int rl = tid >> 6;
    int t  = tid & 63;
    float2* Sr = S + rl * 568;

    int prow = blockIdx.x * 4 + rl;
    int pi   = prow >> 9;
    int r0   = prow & (N - 1);
    int bp   = pi / 3;
    int ch   = pi - 3 * bp;
    const float* xre = x + (size_t)(6 * bp + ch) * PLANE + (size_t)r0 * N;
    const float* xim = xre + (size_t)3 * PLANE;
    int g     = t >> 3;
    int j8    = t & 7;
    int slotA = (j8 + g) & 7;          // pattern-A slot (constant per thread)
    int baseC = 8 * t + 8 * g;         // SK(8t)

    float2 w64, w8;
    sincospif(-(float)t * (1.0f / 256.0f), &w64.y, &w64.x);
    sincospif(-(float)j8 * (1.0f / 32.0f), &w8.y, &w8.x);

    float2 v[8];
    #pragma unroll
    for (int q = 0; q < 8; ++q) {
        int p = t + (q << 6);
        v[q] = make_float2(xre[p], xim[p]);
    }

    // stage m=64
    dft8<false>(v);
    twiddle_out(v, w64);
    #pragma unroll
    for (int r = 0; r < 8; ++r) Sr[72 * r + 8 * g + slotA] = v[r];
    __syncthreads();
    #pragma unroll
    for (int q = 0; q < 8; ++q) v[q] = Sr[72 * g + 8 * q + ((j8 + q) & 7)];

    // stage m=8 (store set == just-read set -> no sync before store)
    dft8<false>(v);
    twiddle_out(v, w8);
    #pragma unroll
    for (int r = 0; r < 8; ++r) Sr[72 * g + 8 * r + ((j8 + r) & 7)] = v[r];
    __syncthreads();
    #pragma unroll
    for (int q = 0; q < 8; ++q) v[q] = Sr[baseC + ((q + t) & 7)];

    // stage m=1
    dft8<false>(v);

    uint4* o = (uint4*)(g_spec + (size_t)prow * N + (t << 3));
    o[0] = make_uint4(pack_h2(v[0]), pack_h2(v[1]), pack_h2(v[2]), pack_h2(v[3]));
    o[1] = make_uint4(pack_h2(v[4]), pack_h2(v[5]), pack_h2(v[6]), pack_h2(v[7]));
}

// ---------------------------------------------------------------------------
// Fused column pass: fwd radix-8 DIF -> real weight multiply -> inv radix-8 DIT.
// Block = 8 columns of one packed plane; c = tid&7, u = tid>>3.
// ---------------------------------------------------------------------------
__global__ void __launch_bounds__(512, 3) k_col_fused() {
    __shared__ float2 S[568 * 8];

    int tid  = threadIdx.x;
    int c    = tid & 7;
    int u    = tid >> 3;
    int img  = blockIdx.x >> 6;          // 0..47
    int col0 = (blockIdx.x & 63) << 3;
    int ch   = img % 3;

    unsigned* base = g_spec + (size_t)img * PLANE + col0 + c;
    int g     = u >> 3;
    int j8    = u & 7;
    int slotA = (j8 + g) & 7;
    int baseC = 8 * u + 8 * g;           // SK(8u)

    float2 w64, w8;
    sincospif(-(float)u * (1.0f / 256.0f), &w64.y, &w64.x);
    sincospif(-(float)j8 * (1.0f / 32.0f), &w8.y, &w8.x);

    #define CIDX(a) ((((a)) << 3) | c)

    float2 v[8];
    #pragma unroll
    for (int q = 0; q < 8; ++q) v[q] = unpack_h2(base[(size_t)(u + (q << 6)) * N]);

    // ---- forward: stage m=64 ----
    dft8<false>(v);
    twiddle_out(v, w64);
    #pragma unroll
    for (int r = 0; r < 8; ++r) S[CIDX(72 * r + 8 * g + slotA)] = v[r];
    __syncthreads();
    #pragma unroll
    for (int q = 0; q < 8; ++q) v[q] = S[CIDX(72 * g + 8 * q + ((j8 + q) & 7))];

    // ---- forward: stage m=8 (store set == read set) ----
    dft8<false>(v);
    twiddle_out(v, w8);
    #pragma unroll
    for (int r = 0; r < 8; ++r) S[CIDX(72 * g + 8 * r + ((j8 + r) & 7))] = v[r];
    __syncthreads();
    #pragma unroll
    for (int q = 0; q < 8; ++q) v[q] = S[CIDX(baseC + ((q + u) & 7))];

    // ---- forward m=1 -> weight -> inverse m=1, all in registers ----
    dft8<false>(v);
    const float* wp = g_wbr + (size_t)ch * PLANE + (size_t)(u << 3) * N + col0 + c;
    #pragma unroll
    for (int r = 0; r < 8; ++r) v[r] = cscale(v[r], wp[(size_t)r * N]);
    dft8<true>(v);

    // store back to own contiguous set (same addresses just read: no sync)
    #pragma unroll
    for (int r = 0; r < 8; ++r) S[CIDX(baseC + ((r + u) & 7))] = v[r];
    __syncthreads();
    #pragma unroll
    for (int q = 0; q < 8; ++q) v[q] = S[CIDX(72 * g + 8 * q + ((j8 + q) & 7))];

    // ---- inverse: stage m=8 (store set == read set) ----
    twiddle_in_conj(v, w8);
    dft8<true>(v);
    #pragma unroll
    for (int r = 0; r < 8; ++r) S[CIDX(72 * g + 8 * r + ((j8 + r) & 7))] = v[r];
    __syncthreads();
    #pragma unroll
    for (int q = 0; q < 8; ++q) v[q] = S[CIDX(72 * q + 8 * g + slotA)];

    // ---- inverse: stage m=64 ----
    twiddle_in_conj(v, w64);
    dft8<true>(v);
    #pragma unroll
    for (int r = 0; r < 8; ++r) base[(size_t)(u + (r << 6)) * N] = pack_h2(v[r]);

    #undef CIDX
}

// ---------------------------------------------------------------------------
// Row inverse FFT (radix-8 DIT, digit-reversed half2 input -> natural).
// 4 rows/block (256 threads). fp32 smem, rotated-slot layout.
// ---------------------------------------------------------------------------
__global__ void __launch_bounds__(256, 6) k_row_inv(float* __restrict__ out) {
    __shared__ float2 S[4 * 568];

    int tid = threadIdx.x;
    int rl = tid >> 6;
    int t  = tid & 63;
    float2* Sr = S + rl * 568;

    int prow = blockIdx.x * 4 + rl;
    int pi   = prow >> 9;
    int r0   = prow & (N - 1);
    int bp   = pi / 3;
    int ch   = pi - 3 * bp;
    int g     = t >> 3;
    int j8    = t & 7;
    int slotA = (j8 + g) & 7;
    int baseC = 8 * t + 8 * g;           // SK(8t)

    float2 w64, w8;
    sincospif(-(float)t * (1.0f / 256.0f), &w64.y, &w64.x);
    sincospif(-(float)j8 * (1.0f / 32.0f), &w8.y, &w8.x);

    const uint4* in4 = (const uint4*)(g_spec + (size_t)prow * N + (t << 3));
    float2 v[8];
    {
        uint4 a0 = in4[0], a1 = in4[1];
        v[0] = unpack_h2(a0.x); v[1] = unpack_h2(a0.y);
        v[2] = unpack_h2(a0.z); v[3] = unpack_h2(a0.w);
        v[4] = unpack_h2(a1.x); v[5] = unpack_h2(a1.y);
        v[6] = unpack_h2(a1.z); v[7] = unpack_h2(a1.w);
    }

    // stage m=1; store own contiguous block, rotated slots
    dft8<true>(v);
    #pragma unroll
    for (int r = 0; r < 8; ++r) Sr[baseC + ((r + t) & 7)] = v[r];
    __syncthreads();
    #pragma unroll
    for (int q = 0; q < 8; ++q) v[q] = Sr[72 * g + 8 * q + ((j8 + q) & 7)];

    // stage m=8 (store set == read set)
    twiddle_in_conj(v, w8);
    dft8<true>(v);
    #pragma unroll
    for (int r = 0; r < 8; ++r) Sr[72 * g + 8 * r + ((j8 + r) & 7)] = v[r];
    __syncthreads();
    #pragma unroll
    for (int q = 0; q < 8; ++q) v[q] = Sr[72 * q + 8 * g + slotA];

    // stage m=64
    twiddle_in_conj(v, w64);
    dft8<true>(v);

    float* ore = out + (size_t)(6 * bp + ch) * PLANE + (size_t)r0 * N;
    float* oim = ore + (size_t)3 * PLANE;
    #pragma unroll
    for (int r = 0; r < 8; ++r) {
        int p = t + (r << 6);
        ore[p] = v[r].x;
        oim[p] = v[r].y;
    }
}

// ---------------------------------------------------------------------------
extern "C" void kernel_launch(void* const* d_in, const int* in_sizes, int n_in,
                              void* d_out, int out_size) {
    const float* x = (const float*)d_in[0];
    const float* p = (const float*)d_in[1];
    if (n_in >= 2 && in_sizes[0] < in_sizes[1]) { const float* t = x; x = p; p = t; }
    float* out = (float*)d_out;

    k_weights<<<(3 * PLANE + 255) / 256, 256>>>(p);
    k_row_fwd<<<NPK * N / 4, 256>>>(x);
    k_col_fused<<<NPK * (N / 8), 512>>>();
    k_row_inv<<<NPK * N / 4, 256>>>(out);
}